// round 15
// baseline (speedup 1.0000x reference)
#include <cuda_runtime.h>
#include <cuda_bf16.h>
#include <cstdint>

#define N_IMG   128
#define C_IN    128
#define O_OUT   32
#define HW      56
#define HCH     8                  // h rows per CTA
#define THREADS 512

// A tile xt: 464 slot-rows (w=-1..56), 256B/row = 128 k' (t0: a_hi c0..63, t1: a_lo c0..63)
#define XT_BYTES (464 * 256)       // 118784
#define B_OFF    XT_BYTES          // 16B aligned
// B: 3 kw x 192 k' rows x 80B (32 o bf16 + pad)
#define B_BYTES  (3 * 192 * 80)    // 46080
#define SMEM_TOTAL (XT_BYTES + B_BYTES)   // 164864

#define SB_STRIDE 461              // stage buffer float stride per o

typedef uint32_t u32;
typedef uint64_t u64;
typedef unsigned short u16;

static __device__ __forceinline__ u32 smem_u32(const void* p) {
    u32 a;
    asm("{ .reg .u64 t; cvta.to.shared.u64 t, %1; cvt.u32.u64 %0, t; }" : "=r"(a) : "l"(p));
    return a;
}
// swizzled byte offset of (slot, kbyte) in xt; 16 blocks of 16B per 256B row,
// XOR low-3 block bits with (slot ^ slot>>3) -> conflict-free for both
// consecutive-slot (ldmatrix) and stride-8-slot (build) access.
static __device__ __forceinline__ u32 xoff(int slot, int kb) {
    int blk = kb >> 4;
    int sw  = (blk & 8) | ((blk ^ slot ^ (slot >> 3)) & 7);
    return (u32)(slot * 256 + (sw << 4) + (kb & 15));
}

static __device__ __forceinline__ void ldsm_x4(u32 addr, u32& r0, u32& r1, u32& r2, u32& r3) {
    asm volatile("ldmatrix.sync.aligned.m8n8.x4.shared.b16 {%0,%1,%2,%3}, [%4];"
                 : "=r"(r0), "=r"(r1), "=r"(r2), "=r"(r3) : "r"(addr));
}
static __device__ __forceinline__ void ldsm_x2t(u32 addr, u32& r0, u32& r1) {
    asm volatile("ldmatrix.sync.aligned.m8n8.x2.trans.shared.b16 {%0,%1}, [%2];"
                 : "=r"(r0), "=r"(r1) : "r"(addr));
}
static __device__ __forceinline__ void mma16816(float* c, u32 a0, u32 a1, u32 a2, u32 a3,
                                                u32 b0, u32 b1) {
    asm volatile("mma.sync.aligned.m16n8k16.row.col.f32.bf16.bf16.f32 "
                 "{%0,%1,%2,%3}, {%4,%5,%6,%7}, {%8,%9}, {%0,%1,%2,%3};"
                 : "+f"(c[0]), "+f"(c[1]), "+f"(c[2]), "+f"(c[3])
                 : "r"(a0), "r"(a1), "r"(a2), "r"(a3), "r"(b0), "r"(b1));
}

__global__ __launch_bounds__(THREADS, 1)
void conv1x3_hmma_kernel(const float* __restrict__ x,
                         const float* __restrict__ wgt,
                         float* __restrict__ out) {
    extern __shared__ char smem[];
    const u32 sb = smem_u32(smem);
    float* sbuf = (float*)smem;

    const int tid = threadIdx.x;
    const int wid = tid >> 5;
    const int lid = tid & 31;
    const int n   = blockIdx.y;
    const int h0  = blockIdx.x * HCH;

    const int nt  = wid & 3;        // n8 tile (o block)
    const int mtb = wid >> 2;       // m-tile group base

    // ---- zero halo rows (slots 0-7 = w=-1, 456-463 = w=56); stays zero both chunks ----
    for (int i = tid; i < 16 * 64; i += THREADS) {
        int rr   = i >> 6;
        int slot = rr < 8 ? rr : (448 + rr);
        *(u32*)(smem + slot * 256 + ((i & 63) << 2)) = 0u;
    }

    float acc[7][4];
    #pragma unroll
    for (int j = 0; j < 7; ++j)
        #pragma unroll
        for (int q = 0; q < 4; ++q) acc[j][q] = 0.f;

    for (int chunk = 0; chunk < 2; ++chunk) {
        __syncthreads();   // halo-zero done / previous chunk's MMA reads done

        // ---- build B: rows k'=t*64+c, t0,t1 -> w_hi, t2 -> w_lo ----
        for (int i = tid; i < 3 * 192 * 32; i += THREADS) {
            int o  = i & 31;
            int k  = (i >> 5) % 192;
            int kw = i / (192 * 32);
            int t  = k >> 6;
            int c  = k & 63;
            float v = wgt[((size_t)o * C_IN + chunk * 64 + c) * 3 + kw];
            __nv_bfloat16 hb = __float2bfloat16(v);
            u16 val;
            if (t < 2) val = __bfloat16_as_ushort(hb);
            else       val = __bfloat16_as_ushort(__float2bfloat16(v - __bfloat162float(hb)));
            *(u16*)(smem + B_OFF + (kw * 192 + k) * 80 + o * 2) = val;
        }

        // ---- build xt: a_hi at kbyte 2c (t0), a_lo at 128+2c (t1) ----
        for (int i = tid; i < 64 * 448; i += THREADS) {
            int c = i / 448;
            int p = i - c * 448;
            int r = p / HW;
            int w = p - r * HW;
            int slot = w * 8 + 8 + r;
            int hsrc = (h0 + r + HW - 1) % HW;   // roll(+1) folded in
            float v = x[(((size_t)n * C_IN + chunk * 64 + c) * HW + hsrc) * HW + w];
            __nv_bfloat16 hb = __float2bfloat16(v);
            __nv_bfloat16 lb = __float2bfloat16(v - __bfloat162float(hb));
            *(u16*)(smem + xoff(slot, 2 * c))       = __bfloat16_as_ushort(hb);
            *(u16*)(smem + xoff(slot, 128 + 2 * c)) = __bfloat16_as_ushort(lb);
        }
        __syncthreads();

        // ---- MMA: 12 k16-tiles; kt 0-3: a_hi x w_hi, 4-7: a_lo x w_hi, 8-11: a_hi x w_lo ----
        #pragma unroll 1
        for (int kt = 0; kt < 12; ++kt) {
            const int kb0 = (kt < 4) ? kt * 32 : (kt < 8 ? 128 + (kt - 4) * 32 : (kt - 8) * 32);

            u32 bfr[3][2];
            #pragma unroll
            for (int kw = 0; kw < 3; ++kw) {
                int row = kw * 192 + kt * 16 + (lid & 15);
                ldsm_x2t(sb + B_OFF + row * 80 + nt * 16, bfr[kw][0], bfr[kw][1]);
            }

            #pragma unroll
            for (int j = 0; j < 7; ++j) {
                const int s0 = (mtb * 7 + j) * 16;
                u32 rl0, rl1, rl2, rl3, rh0, rh1, rh2, rh3;
                ldsm_x4(sb + xoff(s0 + lid, kb0),      rl0, rl1, rl2, rl3);
                ldsm_x4(sb + xoff(s0 + lid, kb0 + 16), rh0, rh1, rh2, rh3);
                mma16816(acc[j], rl0, rl1, rh0, rh1, bfr[0][0], bfr[0][1]);
                mma16816(acc[j], rl1, rl2, rh1, rh2, bfr[1][0], bfr[1][1]);
                mma16816(acc[j], rl2, rl3, rh2, rh3, bfr[2][0], bfr[2][1]);
            }
        }
    }
    __syncthreads();   // all MMA reads of xt done; reuse smem as stage buffer

    // ---- epilogue: stage 16 o at a time in smem, store coalesced ----
    const int r0 = lid >> 2;
    const int c0 = (lid & 3) * 2;
    for (int half = 0; half < 2; ++half) {
        if ((nt >> 1) == half) {
            const int ob = (nt & 1) * 8 + c0;
            #pragma unroll
            for (int j = 0; j < 7; ++j) {
                const int mt = mtb * 7 + j;
                const int w0 = 2 * mt;
                float* p0 = sbuf + r0 * HW + w0;
                p0[(ob)     * SB_STRIDE]     = acc[j][0];
                p0[(ob + 1) * SB_STRIDE]     = acc[j][1];
                p0[(ob)     * SB_STRIDE + 1] = acc[j][2];
                p0[(ob + 1) * SB_STRIDE + 1] = acc[j][3];
            }
        }
        __syncthreads();
        for (int i = tid; i < 16 * 448; i += THREADS) {
            int orel = i / 448;
            int rem  = i - orel * 448;
            int r    = rem / HW;
            int w    = rem - r * HW;
            out[((size_t)n * O_OUT + half * 16 + orel) * (HW * HW)
                + (size_t)(h0 + r) * HW + w] = sbuf[orel * SB_STRIDE + rem];
        }
        __syncthreads();
    }
}

extern "C" void kernel_launch(void* const* d_in, const int* in_sizes, int n_in,
                              void* d_out, int out_size) {
    const float* x = (const float*)d_in[0];
    const float* w = (const float*)d_in[1];
    float* out = (float*)d_out;

    cudaFuncSetAttribute(conv1x3_hmma_kernel,
                         cudaFuncAttributeMaxDynamicSharedMemorySize, SMEM_TOTAL);

    dim3 grid(HW / HCH, N_IMG);   // (7, 128)
    conv1x3_hmma_kernel<<<grid, THREADS, SMEM_TOTAL>>>(x, w, out);
}

// round 16
// speedup vs baseline: 2.2613x; 2.2613x over previous
#include <cuda_runtime.h>
#include <cstdint>

#define HW      56
#define C_IN    128
#define O_OUT   32
#define HCH     8
#define THREADS 512

#define A_OFF   0
#define A_BYTES (464 * 256)            // slots 0..463, 64 tf32 (256B) per row
#define B_OFF   A_BYTES
#define B_ROW   160                    // 40 floats per k-row (conflict-free pad)
#define B_BYTES (3 * 64 * B_ROW)       // 30720
#define SMEM_TOTAL (B_OFF + B_BYTES)   // 149504

typedef uint32_t u32;

static __device__ __forceinline__ u32 smem_u32(const void* p) {
    u32 a;
    asm("{ .reg .u64 t; cvta.to.shared.u64 t, %1; cvt.u32.u64 %0, t; }" : "=r"(a) : "l"(p));
    return a;
}
static __device__ __forceinline__ u32 f2tf32(float v) {
    u32 t;
    asm("cvt.rna.tf32.f32 %0, %1;" : "=r"(t) : "f"(v));
    return t;
}
static __device__ __forceinline__ u32 lds32(u32 a) {
    u32 v;
    asm volatile("ld.shared.b32 %0, [%1];" : "=r"(v) : "r"(a));
    return v;
}
static __device__ __forceinline__ void sts32(u32 a, u32 v) {
    asm volatile("st.shared.b32 [%0], %1;" :: "r"(a), "r"(v));
}
static __device__ __forceinline__ void mma_tf32(float* c, u32 a0, u32 a1, u32 a2, u32 a3,
                                                u32 b0, u32 b1) {
    asm volatile("mma.sync.aligned.m16n8k8.row.col.f32.tf32.tf32.f32 "
                 "{%0,%1,%2,%3},{%4,%5,%6,%7},{%8,%9},{%0,%1,%2,%3};"
                 : "+f"(c[0]), "+f"(c[1]), "+f"(c[2]), "+f"(c[3])
                 : "r"(a0), "r"(a1), "r"(a2), "r"(a3), "r"(b0), "r"(b1));
}

__global__ __launch_bounds__(THREADS, 1)
void conv1x3_tf32_kernel(const float* __restrict__ x,
                         const float* __restrict__ wgt,
                         float* __restrict__ out) {
    extern __shared__ char smem[];
    const u32 sb = smem_u32(smem);

    const int tid = threadIdx.x;
    const int wid = tid >> 5;
    const int lid = tid & 31;
    const int n   = blockIdx.y;
    const int h0  = blockIdx.x * HCH;

    const int nt  = wid & 3;     // o-tile of 8
    const int mtb = wid >> 2;    // m-tile group (7 m16 tiles each)

    // ---- zero halo slot rows (w=-1 -> slots 0..7, w=56 -> slots 456..463) ----
    for (int i = tid; i < 1024; i += THREADS) {
        int b = i >> 6;
        int slot = (b < 8) ? b : 448 + b;
        ((u32*)smem)[slot * 64 + (i & 63)] = 0u;
    }

    // ---- per-thread build setup (division only here) ----
    int br = 0, bw = 0, bslot = 0;
    u32 brow = 0, bsx = 0;
    const float* gA = nullptr;
    const float* gB = nullptr;
    u32 bB = 0;
    if (tid < 448) {
        br = tid / 56; bw = tid - br * 56;
        bslot = (bw + 1) * 8 + br;
        brow  = sb + A_OFF + bslot * 256;
        bsx   = (u32)(bslot ^ (bslot >> 3));
        int hsrc = h0 + br - 1; if (hsrc < 0) hsrc += HW;
        gA = x + ((size_t)(n * C_IN) * HW + hsrc) * HW + bw;
    } else {
        int t = tid - 448;
        int o = t & 31, half = t >> 5;
        gB = wgt + o * (C_IN * 3) + half * 96;
        bB = sb + B_OFF + (u32)(o * 4 + half * 32 * B_ROW);
    }

    float acc[7][4];
    #pragma unroll
    for (int j = 0; j < 7; ++j)
        #pragma unroll
        for (int q = 0; q < 4; ++q) acc[j][q] = 0.f;

    #pragma unroll 1
    for (int chunk = 0; chunk < 2; ++chunk) {
        if (chunk) __syncthreads();     // prior MMA reads done before overwrite

        // ---- build A: 448 threads, fixed pixel, loop c (stride-3136 coalesced LDG) ----
        if (tid < 448) {
            const float* gp = gA + (size_t)chunk * 64 * HW * HW;
            #pragma unroll 8
            for (int c = 0; c < 64; ++c) {
                u32 t = f2tf32(gp[(size_t)c * (HW * HW)]);
                int blk = c >> 2;
                u32 off = (u32)((((blk & 8) | ((blk ^ (int)bsx) & 7)) << 4) + ((c & 3) << 2));
                sts32(brow + off, t);
            }
        } else {
            // ---- build B on warps 14-15: B[kw][k][o] = wgt[o][chunk*64+k][kw] ----
            const float* gp = gB + chunk * 192;
            #pragma unroll
            for (int kw = 0; kw < 3; ++kw) {
                #pragma unroll 8
                for (int kk = 0; kk < 32; ++kk) {
                    u32 t = f2tf32(gp[kk * 3 + kw]);
                    sts32(bB + (u32)((kw * 64 + kk) * B_ROW), t);
                }
            }
        }
        __syncthreads();

        // ---- mainloop: 7 m16 tiles, 8 k8 tiles, 3 kw taps via slot shift ----
        const u32 bb = sb + B_OFF + (u32)((lid & 3) * B_ROW + (nt * 8 + (lid >> 2)) * 4);

        #pragma unroll
        for (int j = 0; j < 7; ++j) {
            const int mt = mtb * 7 + j;
            u32 abase[4], sx[4];
            #pragma unroll
            for (int g = 0; g < 4; ++g) {
                int slot = mt * 16 + g * 8 + (lid >> 2);
                abase[g] = sb + A_OFF + slot * 256 + (lid & 3) * 4;
                sx[g] = (u32)(slot ^ (slot >> 3));
            }
            #pragma unroll 2
            for (int kt = 0; kt < 8; ++kt) {
                const int b0 = 2 * kt, b1 = 2 * kt + 1;
                u32 a0[4], a1[4];
                #pragma unroll
                for (int g = 0; g < 4; ++g) {
                    u32 o0 = (u32)((((b0 & 8) | ((b0 ^ (int)sx[g]) & 7)) << 4));
                    u32 o1 = (u32)((((b1 & 8) | ((b1 ^ (int)sx[g]) & 7)) << 4));
                    a0[g] = lds32(abase[g] + o0);
                    a1[g] = lds32(abase[g] + o1);
                }
                #pragma unroll
                for (int kw = 0; kw < 3; ++kw) {
                    u32 ba = bb + (u32)((kw * 64 + kt * 8) * B_ROW);
                    u32 w0 = lds32(ba);
                    u32 w1 = lds32(ba + 4 * B_ROW);
                    mma_tf32(acc[j], a0[kw], a0[kw + 1], a1[kw], a1[kw + 1], w0, w1);
                }
            }
        }
    }
    __syncthreads();   // all MMA reads done; reuse A region as stage buffer

    // ---- epilogue: stage (pad-513) then linear coalesced store ----
    float* stg = (float*)smem;
    {
        const int g = lid >> 2;
        const int o = nt * 8 + 2 * (lid & 3);
        #pragma unroll
        for (int j = 0; j < 7; ++j) {
            const int mt = mtb * 7 + j;
            const int p0 = g * 56 + 2 * mt;
            stg[o * 513 + p0]           = acc[j][0];
            stg[(o + 1) * 513 + p0]     = acc[j][1];
            stg[o * 513 + p0 + 1]       = acc[j][2];
            stg[(o + 1) * 513 + p0 + 1] = acc[j][3];
        }
    }
    __syncthreads();
    if (tid < 448) {
        float* ob = out + ((size_t)n * O_OUT) * (HW * HW) + h0 * HW + tid;
        #pragma unroll 4
        for (int o = 0; o < O_OUT; ++o)
            ob[(size_t)o * (HW * HW)] = stg[o * 513 + tid];
    }
}

extern "C" void kernel_launch(void* const* d_in, const int* in_sizes, int n_in,
                              void* d_out, int out_size) {
    const float* x = (const float*)d_in[0];
    const float* w = (const float*)d_in[1];
    float* out = (float*)d_out;

    cudaFuncSetAttribute(conv1x3_tf32_kernel,
                         cudaFuncAttributeMaxDynamicSharedMemorySize, SMEM_TOTAL);

    dim3 grid(HW / HCH, 128);   // (7, 128)
    conv1x3_tf32_kernel<<<grid, THREADS, SMEM_TOTAL>>>(x, w, out);
}

// round 17
// speedup vs baseline: 3.0586x; 1.3526x over previous
#include <cuda_runtime.h>
#include <cstdint>

#define HW      56
#define C_IN    128
#define O_OUT   32
#define HCH     8
#define THREADS 512

#define A_OFF   0
#define A_BYTES (464 * 256)            // slots 0..463, 64 tf32 per row (256B)
#define B_OFF   A_BYTES
#define B_ROW   160                    // 40 floats per k-row (conflict-free pad)
#define B_BYTES (3 * 64 * B_ROW)       // 30720
#define SMEM_TOTAL (B_OFF + B_BYTES)   // 149504

typedef uint32_t u32;

static __device__ __forceinline__ u32 smem_u32(const void* p) {
    u32 a;
    asm("{ .reg .u64 t; cvta.to.shared.u64 t, %1; cvt.u32.u64 %0, t; }" : "=r"(a) : "l"(p));
    return a;
}
static __device__ __forceinline__ u32 f2tf32(float v) {
    u32 t;
    asm("cvt.rna.tf32.f32 %0, %1;" : "=r"(t) : "f"(v));
    return t;
}
static __device__ __forceinline__ u32 lds32(u32 a) {
    u32 v;
    asm volatile("ld.shared.b32 %0, [%1];" : "=r"(v) : "r"(a));
    return v;
}
static __device__ __forceinline__ void sts32(u32 a, u32 v) {
    asm volatile("st.shared.b32 [%0], %1;" :: "r"(a), "r"(v));
}
static __device__ __forceinline__ void sts128(u32 a, u32 v0, u32 v1, u32 v2, u32 v3) {
    asm volatile("st.shared.v4.b32 [%0], {%1,%2,%3,%4};"
                 :: "r"(a), "r"(v0), "r"(v1), "r"(v2), "r"(v3));
}
static __device__ __forceinline__ void mma_tf32(float* c, u32 a0, u32 a1, u32 a2, u32 a3,
                                                u32 b0, u32 b1) {
    asm volatile("mma.sync.aligned.m16n8k8.row.col.f32.tf32.tf32.f32 "
                 "{%0,%1,%2,%3},{%4,%5,%6,%7},{%8,%9},{%0,%1,%2,%3};"
                 : "+f"(c[0]), "+f"(c[1]), "+f"(c[2]), "+f"(c[3])
                 : "r"(a0), "r"(a1), "r"(a2), "r"(a3), "r"(b0), "r"(b1));
}

__global__ __launch_bounds__(THREADS, 1)
void conv1x3_tf32_kernel(const float* __restrict__ x,
                         const float* __restrict__ wgt,
                         float* __restrict__ out) {
    extern __shared__ char smem[];
    const u32 sb = smem_u32(smem);

    const int tid = threadIdx.x;
    const int wid = tid >> 5;
    const int lid = tid & 31;
    const int n   = blockIdx.y;
    const int h0  = blockIdx.x * HCH;

    // ---- zero halo slot rows (w=-1 -> slots 0..7, w=56 -> slots 456..463) ----
    for (int i = tid; i < 1024; i += THREADS) {
        int b = i >> 6;
        int slot = (b < 8) ? b : 448 + b;
        ((u32*)smem)[slot * 64 + (i & 63)] = 0u;
    }

    // ---- builder setup ----
    u32 brow = 0;
    int bsx = 0;
    const float* gA = nullptr;
    const float* gB = nullptr;
    u32 bB = 0;
    int bhalf = 0;
    if (tid < 448) {
        int br = tid / 56, bw = tid - br * 56;
        int bslot = (bw + 1) * 8 + br;
        brow = sb + A_OFF + bslot * 256;
        bsx  = (bslot ^ (bslot >> 3)) & 7;
        int hsrc = h0 + br - 1; if (hsrc < 0) hsrc += HW;
        gA = x + ((size_t)(n * C_IN) * HW + hsrc) * HW + bw;
    } else {
        int t = tid - 448;
        int o = t & 31;
        bhalf = t >> 5;
        gB = wgt + o * (C_IN * 3);
        bB = sb + B_OFF + (u32)(o * 4);
    }

    // ---- compute-warp setup: warp wid<14 owns m-tiles {2wid, 2wid+1}, all 32 o ----
    u32 abase[2][4];
    int sxg[2][4];
    u32 bbase = sb + B_OFF + (u32)((lid & 3) * B_ROW + (lid >> 2) * 4);
    if (wid < 14) {
        #pragma unroll
        for (int j = 0; j < 2; ++j)
            #pragma unroll
            for (int g = 0; g < 4; ++g) {
                int slot = wid * 32 + j * 16 + g * 8 + (lid >> 2);
                abase[j][g] = sb + A_OFF + slot * 256 + (lid & 3) * 4;
                sxg[j][g] = (slot ^ (slot >> 3)) & 7;
            }
    }

    float acc[2][4][4];
    #pragma unroll
    for (int j = 0; j < 2; ++j)
        #pragma unroll
        for (int q = 0; q < 4; ++q)
            #pragma unroll
            for (int e = 0; e < 4; ++e) acc[j][q][e] = 0.f;

    #pragma unroll 1
    for (int chunk = 0; chunk < 2; ++chunk) {
        __syncthreads();   // halo-zero done / prior chunk's MMA reads done

        if (tid < 448) {
            // ---- build A: 64 LDG (stride 3136, coalesced) -> 16 STS.128 ----
            const float* gp = gA + (size_t)chunk * 64 * (HW * HW);
            #pragma unroll
            for (int b = 0; b < 16; ++b) {
                float v0 = gp[(size_t)(4 * b + 0) * (HW * HW)];
                float v1 = gp[(size_t)(4 * b + 1) * (HW * HW)];
                float v2 = gp[(size_t)(4 * b + 2) * (HW * HW)];
                float v3 = gp[(size_t)(4 * b + 3) * (HW * HW)];
                u32 off = (u32)((((b ^ bsx) & 7) | (b & 8)) << 4);
                sts128(brow + off, f2tf32(v0), f2tf32(v1), f2tf32(v2), f2tf32(v3));
            }
        } else {
            // ---- build B (warps 14-15): B[kw][k][o] = wgt[o][chunk*64+k][kw] ----
            const float* gp = gB + (chunk * 64 + bhalf * 32) * 3;
            #pragma unroll
            for (int kw = 0; kw < 3; ++kw) {
                u32 bd = bB + (u32)((kw * 64 + bhalf * 32) * B_ROW);
                #pragma unroll 8
                for (int kk = 0; kk < 32; ++kk)
                    sts32(bd + (u32)(kk * B_ROW), f2tf32(gp[kk * 3 + kw]));
            }
        }
        __syncthreads();

        if (wid < 14) {
            #pragma unroll
            for (int kt = 0; kt < 8; ++kt) {
                // ---- B frags once per kt: 3 kw x 4 q x 2 halves ----
                u32 bfr[3][4][2];
                #pragma unroll
                for (int kw = 0; kw < 3; ++kw)
                    #pragma unroll
                    for (int q = 0; q < 4; ++q) {
                        u32 ba = bbase + (u32)((kw * 64 + kt * 8) * B_ROW + q * 32);
                        bfr[kw][q][0] = lds32(ba);
                        bfr[kw][q][1] = lds32(ba + 4 * B_ROW);
                    }
                const int b0 = 2 * kt, b1 = 2 * kt + 1;
                #pragma unroll
                for (int j = 0; j < 2; ++j) {
                    u32 a0[4], a1[4];
                    #pragma unroll
                    for (int g = 0; g < 4; ++g) {
                        u32 o0 = (u32)((((b0 ^ sxg[j][g]) & 7) | (b0 & 8)) << 4);
                        u32 o1 = (u32)((((b1 ^ sxg[j][g]) & 7) | (b1 & 8)) << 4);
                        a0[g] = lds32(abase[j][g] + o0);
                        a1[g] = lds32(abase[j][g] + o1);
                    }
                    #pragma unroll
                    for (int q = 0; q < 4; ++q)
                        #pragma unroll
                        for (int kw = 0; kw < 3; ++kw)
                            mma_tf32(acc[j][q], a0[kw], a0[kw + 1], a1[kw], a1[kw + 1],
                                     bfr[kw][q][0], bfr[kw][q][1]);
                }
            }
        }
    }
    __syncthreads();   // all MMA reads done; reuse smem as stage buffer

    // ---- epilogue: stage (pad-513) then linear coalesced store ----
    float* stg = (float*)smem;
    if (wid < 14) {
        const int r  = lid >> 2;
        const int ow = 2 * (lid & 3);
        #pragma unroll
        for (int j = 0; j < 2; ++j) {
            const int mt = wid * 2 + j;
            const int p0 = r * 56 + 2 * mt;
            #pragma unroll
            for (int q = 0; q < 4; ++q) {
                const int o = q * 8 + ow;
                stg[o * 513 + p0]           = acc[j][q][0];
                stg[(o + 1) * 513 + p0]     = acc[j][q][1];
                stg[o * 513 + p0 + 1]       = acc[j][q][2];
                stg[(o + 1) * 513 + p0 + 1] = acc[j][q][3];
            }
        }
    }
    __syncthreads();
    if (tid < 448) {
        float* ob = out + ((size_t)n * O_OUT) * (HW * HW) + h0 * HW + tid;
        #pragma unroll 4
        for (int o = 0; o < O_OUT; ++o)
            ob[(size_t)o * (HW * HW)] = stg[o * 513 + tid];
    }
}

extern "C" void kernel_launch(void* const* d_in, const int* in_sizes, int n_in,
                              void* d_out, int out_size) {
    const float* x = (const float*)d_in[0];
    const float* w = (const float*)d_in[1];
    float* out = (float*)d_out;

    cudaFuncSetAttribute(conv1x3_tf32_kernel,
                         cudaFuncAttributeMaxDynamicSharedMemorySize, SMEM_TOTAL);

    dim3 grid(HW / HCH, 128);   // (7, 128)
    conv1x3_tf32_kernel<<<grid, THREADS, SMEM_TOTAL>>>(x, w, out);
}